// round 4
// baseline (speedup 1.0000x reference)
#include <cuda_runtime.h>

// ---------------- problem constants ----------------
#define B_   32
#define C_   256        // Cin
#define O_   256        // Cout
#define H_   49
#define P_   (H_ * H_)  // 2401 pixels
#define PAD  51         // 49 + 1 halo each side
#define M_   (B_ * P_)  // 76832 GEMM rows
#define K_   (7 * C_)   // 1792

// DIRS = {(0,0),(1,0),(0,1),(-1,1),(-1,0),(0,-1),(1,-1)}; offset = (dy*PAD+dx)*C_
__constant__ int c_tapoff[7] = { 0, 13056, 256, -12800, -13056, -256, 12800 };

// ---------------- scratch (device globals; zero-initialized at load) ----------------
__device__ float g_xpad[B_ * PAD * PAD * C_];   // [B,51,51,C] channels-last, ~85 MB
__device__ float g_wt[7 * C_ * O_];             // [n,c,o]

// ---------------- prep: zero padded buffer ----------------
__global__ void zero_xpad_kernel() {
    const int n4 = (B_ * PAD * PAD * C_) / 4;
    int i = blockIdx.x * blockDim.x + threadIdx.x;
    if (i < n4) ((float4*)g_xpad)[i] = make_float4(0.f, 0.f, 0.f, 0.f);
}

// ---------------- prep: weight [O,C,7] -> [n,c,o] ----------------
__global__ void prep_w_kernel(const float* __restrict__ w) {
    int idx = blockIdx.x * blockDim.x + threadIdx.x;
    if (idx < 7 * C_ * O_) {
        int o = idx & 255;
        int c = (idx >> 8) & 255;
        int n = idx >> 16;
        g_wt[idx] = w[(o * C_ + c) * 7 + n];
    }
}

// ---------------- prep: x [B,C,H,W] -> masked channels-last padded xpad ----------------
// smem transpose: coalesced read over hw, coalesced write over c.
__global__ void prep_x_kernel(const float* __restrict__ x) {
    __shared__ float tile[32][33];
    const int b   = blockIdx.z;
    const int c0  = blockIdx.y * 32;
    const int hw0 = blockIdx.x * 32;
    const int tx = threadIdx.x, ty = threadIdx.y;   // (32, 8)

#pragma unroll
    for (int i = 0; i < 4; i++) {
        int c  = c0 + ty + i * 8;
        int hw = hw0 + tx;
        tile[ty + i * 8][tx] = (hw < P_) ? x[(b * C_ + c) * P_ + hw] : 0.f;
    }
    __syncthreads();
#pragma unroll
    for (int i = 0; i < 4; i++) {
        int hw = hw0 + ty + i * 8;
        if (hw < P_) {
            int h = hw / H_;
            int w = hw - h * H_;
            bool mk = (unsigned)(h + w - 24) <= 48u;   // |h+w-48| <= 24
            float v = mk ? tile[tx][ty + i * 8] : 0.f;
            g_xpad[((b * PAD + h + 1) * PAD + (w + 1)) * C_ + c0 + tx] = v;
        }
    }
}

// ---------------- main: implicit GEMM 128x128x16, 256 threads, 8x8/thread ----------------
__global__ __launch_bounds__(256, 2)
void hexconv_gemm_kernel(const float* __restrict__ bias, float* __restrict__ out) {
    __shared__ float As[16][128];
    __shared__ float Bs[16][128];
    __shared__ int   rbase[128];

    const int tid = threadIdx.x;
    const int r0  = blockIdx.x * 128;
    const int nb  = blockIdx.y;                 // N tile: 0 or 1

    if (tid < 128) {
        int r = r0 + tid;
        if (r >= M_) r = M_ - 1;                // clamp padded rows (writes guarded later)
        int b  = r / P_;
        int hw = r - b * P_;
        int h  = hw / H_;
        int w  = hw - h * H_;
        rbase[tid] = ((b * PAD + h + 1) * PAD + (w + 1)) * C_;
    }
    __syncthreads();

    const int tm = tid >> 4;                    // 0..15
    const int tn = tid & 15;                    // 0..15

    float acc[8][8];
#pragma unroll
    for (int i = 0; i < 8; i++)
#pragma unroll
        for (int j = 0; j < 8; j++) acc[i][j] = 0.f;

    // A-load mapping: 512 float4 slots = 128 rows x 4 quads; thread covers (row, row+64)
    const int arow = tid >> 2;                  // 0..63
    const int aq   = (tid & 3) * 4;             // 0,4,8,12
    // B-load mapping: 16 k-rows x 32 float4s; thread covers (kk, kk+8)
    const int bk   = tid >> 5;                  // 0..7
    const int bo   = (tid & 31) * 4;

    const int ra0 = rbase[arow];
    const int ra1 = rbase[arow + 64];

    for (int k0 = 0; k0 < K_; k0 += 16) {
        const int tap = k0 >> 8;
        const int c0  = k0 & 255;
        const int off = c_tapoff[tap] + c0 + aq;

        // global fetches (in regs while previous tile computes)
        float4 a0 = *(const float4*)(g_xpad + ra0 + off);
        float4 a1 = *(const float4*)(g_xpad + ra1 + off);
        float4 b0 = *(const float4*)(g_wt + (k0 + bk)     * O_ + nb * 128 + bo);
        float4 b1 = *(const float4*)(g_wt + (k0 + bk + 8) * O_ + nb * 128 + bo);

        __syncthreads();   // previous tile fully consumed
        As[aq + 0][arow] = a0.x; As[aq + 1][arow] = a0.y;
        As[aq + 2][arow] = a0.z; As[aq + 3][arow] = a0.w;
        As[aq + 0][arow + 64] = a1.x; As[aq + 1][arow + 64] = a1.y;
        As[aq + 2][arow + 64] = a1.z; As[aq + 3][arow + 64] = a1.w;
        *(float4*)&Bs[bk][bo]     = b0;
        *(float4*)&Bs[bk + 8][bo] = b1;
        __syncthreads();

#pragma unroll
        for (int kk = 0; kk < 16; kk++) {
            float4 av0 = *(const float4*)&As[kk][tm * 8];
            float4 av1 = *(const float4*)&As[kk][tm * 8 + 4];
            float4 bv0 = *(const float4*)&Bs[kk][tn * 8];
            float4 bv1 = *(const float4*)&Bs[kk][tn * 8 + 4];
            float a[8] = { av0.x, av0.y, av0.z, av0.w, av1.x, av1.y, av1.z, av1.w };
            float b[8] = { bv0.x, bv0.y, bv0.z, bv0.w, bv1.x, bv1.y, bv1.z, bv1.w };
#pragma unroll
            for (int i = 0; i < 8; i++)
#pragma unroll
                for (int j = 0; j < 8; j++)
                    acc[i][j] += a[i] * b[j];
        }
    }

    // epilogue: bias + mask, scatter to [B,O,H,W]
    const int ob = nb * 128 + tn * 8;
    float4 bvlo = *(const float4*)(bias + ob);
    float4 bvhi = *(const float4*)(bias + ob + 4);
    float bv[8] = { bvlo.x, bvlo.y, bvlo.z, bvlo.w, bvhi.x, bvhi.y, bvhi.z, bvhi.w };

#pragma unroll
    for (int i = 0; i < 8; i++) {
        int r = r0 + tm * 8 + i;
        if (r < M_) {
            int b  = r / P_;
            int hw = r - b * P_;
            int h  = hw / H_;
            int w  = hw - h * H_;
            bool mk = (unsigned)(h + w - 24) <= 48u;
#pragma unroll
            for (int j = 0; j < 8; j++) {
                float v = mk ? (acc[i][j] + bv[j]) : 0.f;
                out[(b * O_ + ob + j) * P_ + hw] = v;
            }
        }
    }
}

// ---------------- launcher ----------------
extern "C" void kernel_launch(void* const* d_in, const int* in_sizes, int n_in,
                              void* d_out, int out_size) {
    const float* x    = (const float*)d_in[0];   // [32,256,49,49]
    const float* wgt  = (const float*)d_in[1];   // [256,256,7]
    const float* bias = (const float*)d_in[2];   // [256]
    float* out = (float*)d_out;                  // [32,256,49,49]

    // prep
    {
        int n4 = (B_ * PAD * PAD * C_) / 4;
        zero_xpad_kernel<<<(n4 + 255) / 256, 256>>>();
        int nw = 7 * C_ * O_;
        prep_w_kernel<<<(nw + 255) / 256, 256>>>(wgt);
        dim3 g((P_ + 31) / 32, C_ / 32, B_);
        prep_x_kernel<<<g, dim3(32, 8)>>>(x);
    }

    // main GEMM: grid (ceil(M/128), N/128)
    dim3 grid((M_ + 127) / 128, O_ / 128);
    hexconv_gemm_kernel<<<grid, 256>>>(bias, out);
}

// round 8
// speedup vs baseline: 2.7013x; 2.7013x over previous
#include <cuda_runtime.h>
#include <cstdint>

// ---------------- problem constants ----------------
#define B_    32
#define C_    256
#define O_    256
#define H_    49
#define P_    (H_ * H_)        // 2401
#define PAD   51
#define M_    (B_ * P_)        // 76832
#define KTOT  (7 * C_)         // 1792
#define KC    32               // K per pipeline chunk
#define NCHUNK (KTOT / KC)     // 56
#define STAGES 4
#define MT    128              // M rows per CTA
#define GRID_M ((M_ + MT - 1) / MT)   // 601

#define ASTRIDE 36                      // smem row stride in floats (conflict-free frags)
#define STAGE_F (MT * ASTRIDE)          // 4608 floats per A (or B) stage
#define DYN_SMEM (2 * STAGES * STAGE_F * 4)   // 147456 bytes

// DIRS offsets in padded channels-last space: (dy*PAD+dx)*C_
__constant__ int c_tapoff[7] = { 0, 13056, 256, -12800, -13056, -256, 12800 };

// ---------------- scratch ----------------
__device__ float g_xpad[B_ * PAD * PAD * C_];   // [B,51,51,C] channels-last, tf32-rounded
__device__ float g_wb[O_ * KTOT];               // [o][k], k = tap*256 + c, tf32-rounded

// ---------------- helpers ----------------
__device__ __forceinline__ float to_tf32(float f) {
    uint32_t u;
    asm("cvt.rna.tf32.f32 %0, %1;" : "=r"(u) : "f"(f));
    return __uint_as_float(u);
}
__device__ __forceinline__ void mma8(float* c, const uint32_t* a, const uint32_t* b) {
    asm volatile(
        "mma.sync.aligned.m16n8k8.row.col.f32.tf32.tf32.f32 "
        "{%0,%1,%2,%3}, {%4,%5,%6,%7}, {%8,%9}, {%0,%1,%2,%3};"
        : "+f"(c[0]), "+f"(c[1]), "+f"(c[2]), "+f"(c[3])
        : "r"(a[0]), "r"(a[1]), "r"(a[2]), "r"(a[3]), "r"(b[0]), "r"(b[1]));
}
#define CP_ASYNC16(dst, src) \
    asm volatile("cp.async.cg.shared.global [%0], [%1], 16;" :: "r"(dst), "l"(src))
#define CP_COMMIT() asm volatile("cp.async.commit_group;")
#define CP_WAIT(n)  asm volatile("cp.async.wait_group %0;" :: "n"(n))

// ---------------- prep kernels ----------------
__global__ void zero_halo_kernel() {      // zero only the 200 boundary cells of xpad
    int t = blockIdx.x * blockDim.x + threadIdx.x;
    const int total = B_ * 200 * 64;
    if (t >= total) return;
    int q = t & 63;
    int cell = (t >> 6) % 200;
    int b = t / (200 * 64);
    int h, w;
    if      (cell < 51)  { h = 0;  w = cell; }
    else if (cell < 102) { h = 50; w = cell - 51; }
    else if (cell < 151) { h = cell - 101; w = 0; }
    else                 { h = cell - 150; w = 50; }
    ((float4*)(g_xpad + ((size_t)(b * PAD + h) * PAD + w) * C_))[q] =
        make_float4(0.f, 0.f, 0.f, 0.f);
}

__global__ void prep_wb_kernel(const float* __restrict__ w) {
    int idx = blockIdx.x * blockDim.x + threadIdx.x;
    if (idx < O_ * KTOT) {
        int o = idx / KTOT;
        int k = idx - o * KTOT;
        int tap = k >> 8, c = k & 255;
        g_wb[idx] = to_tf32(w[(o * C_ + c) * 7 + tap]);
    }
}

__global__ void prep_x_kernel(const float* __restrict__ x) {
    __shared__ float tile[32][33];
    const int b = blockIdx.z, c0 = blockIdx.y * 32, hw0 = blockIdx.x * 32;
    const int tx = threadIdx.x, ty = threadIdx.y;
#pragma unroll
    for (int i = 0; i < 4; i++) {
        int c = c0 + ty + i * 8, hw = hw0 + tx;
        tile[ty + i * 8][tx] = (hw < P_) ? x[((size_t)b * C_ + c) * P_ + hw] : 0.f;
    }
    __syncthreads();
#pragma unroll
    for (int i = 0; i < 4; i++) {
        int hw = hw0 + ty + i * 8;
        if (hw < P_) {
            int h = hw / H_, w = hw - h * H_;
            bool mk = (unsigned)(h + w - 24) <= 48u;
            float v = mk ? to_tf32(tile[tx][ty + i * 8]) : 0.f;
            g_xpad[((size_t)(b * PAD + h + 1) * PAD + (w + 1)) * C_ + c0 + tx] = v;
        }
    }
}

// ---------------- main: tf32 mma.sync GEMM, 128x128 tile, 4-stage cp.async ----------------
__global__ __launch_bounds__(256)
void hexconv_mma_kernel(const float* __restrict__ bias, float* __restrict__ out) {
    extern __shared__ __align__(16) float smem[];
    float* sA = smem;                     // [STAGES][128][36]
    float* sB = smem + STAGES * STAGE_F;  // [STAGES][128][36]
    __shared__ int rbase[MT];

    const int tid = threadIdx.x, wid = tid >> 5, lane = tid & 31;
    const int r0 = blockIdx.x * MT;
    const int nb = blockIdx.y;            // N tile: o-offset nb*128

    if (tid < MT) {
        int r = r0 + tid;
        if (r >= M_) r = M_ - 1;
        int b = r / P_, hw = r - b * P_, h = hw / H_, w = hw - h * H_;
        rbase[tid] = ((b * PAD + h + 1) * PAD + (w + 1)) * C_;
    }
    __syncthreads();

    // loader mapping: thread covers 4 rows (lrow+32i), one 16B quad per row
    const int lrow = tid >> 3;            // 0..31
    const int lq   = (tid & 7) * 4;       // 0,4,...,28 floats
    int ra[4];
#pragma unroll
    for (int i = 0; i < 4; i++) ra[i] = rbase[lrow + 32 * i];

    const uint32_t sA_u = (uint32_t)__cvta_generic_to_shared(sA);
    const uint32_t sB_u = (uint32_t)__cvta_generic_to_shared(sB);

    // warp tile: 2 (M) x 4 (N) warps, each 64x32
    const int wm = (wid & 1) * 64;
    const int wn = (wid >> 1) * 32;

    float acc[4][4][4];
#pragma unroll
    for (int mi = 0; mi < 4; mi++)
#pragma unroll
        for (int ni = 0; ni < 4; ni++)
#pragma unroll
            for (int j = 0; j < 4; j++) acc[mi][ni][j] = 0.f;

    // ---- pipeline ----
    auto load_stage = [&](int s, int ch) {
        const int k0 = ch * KC;
        const int offA = c_tapoff[k0 >> 8] + (k0 & 255) + lq;
#pragma unroll
        for (int i = 0; i < 4; i++) {
            uint32_t dA = sA_u + (uint32_t)(s * STAGE_F + (lrow + 32 * i) * ASTRIDE + lq) * 4u;
            CP_ASYNC16(dA, g_xpad + ra[i] + offA);
        }
#pragma unroll
        for (int i = 0; i < 4; i++) {
            uint32_t dB = sB_u + (uint32_t)(s * STAGE_F + (lrow + 32 * i) * ASTRIDE + lq) * 4u;
            CP_ASYNC16(dB, g_wb + (size_t)(nb * 128 + lrow + 32 * i) * KTOT + k0 + lq);
        }
    };

#pragma unroll
    for (int s = 0; s < STAGES - 1; s++) { load_stage(s, s); CP_COMMIT(); }

    for (int ch = 0; ch < NCHUNK; ch++) {
        CP_WAIT(STAGES - 2);
        __syncthreads();
        const int pre = ch + STAGES - 1;
        if (pre < NCHUNK) load_stage(pre % STAGES, pre);
        CP_COMMIT();

        const float* A = sA + (ch % STAGES) * STAGE_F;
        const float* Bm = sB + (ch % STAGES) * STAGE_F;
#pragma unroll
        for (int kk = 0; kk < 4; kk++) {
            const int kb = kk * 8 + (lane & 3);
            uint32_t af[4][4], bf[4][2];
#pragma unroll
            for (int mi = 0; mi < 4; mi++) {
                int m0 = wm + mi * 16 + (lane >> 2);
                af[mi][0] = __float_as_uint(A[m0 * ASTRIDE + kb]);
                af[mi][1] = __float_as_uint(A[(m0 + 8) * ASTRIDE + kb]);
                af[mi][2] = __float_as_uint(A[m0 * ASTRIDE + kb + 4]);
                af[mi][3] = __float_as_uint(A[(m0 + 8) * ASTRIDE + kb + 4]);
            }
#pragma unroll
            for (int ni = 0; ni < 4; ni++) {
                int n0 = wn + ni * 8 + (lane >> 2);
                bf[ni][0] = __float_as_uint(Bm[n0 * ASTRIDE + kb]);
                bf[ni][1] = __float_as_uint(Bm[n0 * ASTRIDE + kb + 4]);
            }
#pragma unroll
            for (int mi = 0; mi < 4; mi++)
#pragma unroll
                for (int ni = 0; ni < 4; ni++)
                    mma8(acc[mi][ni], af[mi], bf[ni]);
        }
    }

    // ---- epilogue: acc -> smem [o][m] (stride 132), then coalesced store ----
    __syncthreads();
    float* ep = smem;                     // 128*132 floats = 67.6 KB, fits
#pragma unroll
    for (int mi = 0; mi < 4; mi++) {
        int rrow = wm + mi * 16 + (lane >> 2);
#pragma unroll
        for (int ni = 0; ni < 4; ni++) {
            int o = wn + ni * 8 + 2 * (lane & 3);
            ep[o * 132 + rrow]           = acc[mi][ni][0];
            ep[(o + 1) * 132 + rrow]     = acc[mi][ni][1];
            ep[o * 132 + rrow + 8]       = acc[mi][ni][2];
            ep[(o + 1) * 132 + rrow + 8] = acc[mi][ni][3];
        }
    }
    __syncthreads();

    for (int o = wid; o < 128; o += 8) {
        float bv = __ldg(bias + nb * 128 + o);
#pragma unroll
        for (int mb = 0; mb < 128; mb += 32) {
            int m = mb + lane;
            int r = r0 + m;
            if (r < M_) {
                int b = r / P_, hw = r - b * P_, h = hw / H_, w = hw - h * H_;
                bool mk = (unsigned)(h + w - 24) <= 48u;
                float v = mk ? (ep[o * 132 + m] + bv) : 0.f;
                out[((size_t)b * O_ + nb * 128 + o) * P_ + hw] = v;
            }
        }
    }
}

// ---------------- launcher ----------------
extern "C" void kernel_launch(void* const* d_in, const int* in_sizes, int n_in,
                              void* d_out, int out_size) {
    const float* x    = (const float*)d_in[0];   // [32,256,49,49]
    const float* wgt  = (const float*)d_in[1];   // [256,256,7]
    const float* bias = (const float*)d_in[2];   // [256]
    float* out = (float*)d_out;

    { // prep
        int nh = B_ * 200 * 64;
        zero_halo_kernel<<<(nh + 255) / 256, 256>>>();
        int nw = O_ * KTOT;
        prep_wb_kernel<<<(nw + 255) / 256, 256>>>(wgt);
        dim3 g((P_ + 31) / 32, C_ / 32, B_);
        prep_x_kernel<<<g, dim3(32, 8)>>>(x);
    }

    cudaFuncSetAttribute(hexconv_mma_kernel,
                         cudaFuncAttributeMaxDynamicSharedMemorySize, DYN_SMEM);
    dim3 grid(GRID_M, 2);
    hexconv_mma_kernel<<<grid, 256, DYN_SMEM>>>(bias, out);
}

// round 9
// speedup vs baseline: 3.1663x; 1.1721x over previous
#include <cuda_runtime.h>
#include <cstdint>

// ---------------- problem constants ----------------
#define B_    32
#define C_    256
#define O_    256
#define H_    49
#define P_    (H_ * H_)        // 2401
#define PAD   51
#define M_    (B_ * P_)        // 76832
#define KTOT  (7 * C_)         // 1792
#define KC    32               // K per pipeline chunk
#define NCHUNK (KTOT / KC)     // 56
#define STAGES 3               // 3 stages -> 110.6 KB -> 2 CTAs/SM
#define MT    128              // M rows per CTA
#define GRID_M ((M_ + MT - 1) / MT)   // 601

#define ASTRIDE 36                      // smem row stride in floats (conflict-free frags)
#define STAGE_F (MT * ASTRIDE)          // 4608 floats per A (or B) stage
#define DYN_SMEM (2 * STAGES * STAGE_F * 4)   // 110592 bytes

// DIRS offsets in padded channels-last space: (dy*PAD+dx)*C_
__constant__ int c_tapoff[7] = { 0, 13056, 256, -12800, -13056, -256, 12800 };

// ---------------- scratch ----------------
__device__ float g_xpad[B_ * PAD * PAD * C_];   // [B,51,51,C] channels-last, tf32-rounded
__device__ float g_wb[O_ * KTOT];               // [o][k], k = tap*256 + c, tf32-rounded

// ---------------- helpers ----------------
__device__ __forceinline__ float to_tf32(float f) {
    uint32_t u;
    asm("cvt.rna.tf32.f32 %0, %1;" : "=r"(u) : "f"(f));
    return __uint_as_float(u);
}
__device__ __forceinline__ void mma8(float* c, const uint32_t* a, const uint32_t* b) {
    asm volatile(
        "mma.sync.aligned.m16n8k8.row.col.f32.tf32.tf32.f32 "
        "{%0,%1,%2,%3}, {%4,%5,%6,%7}, {%8,%9}, {%0,%1,%2,%3};"
        : "+f"(c[0]), "+f"(c[1]), "+f"(c[2]), "+f"(c[3])
        : "r"(a[0]), "r"(a[1]), "r"(a[2]), "r"(a[3]), "r"(b[0]), "r"(b[1]));
}
#define CP_ASYNC16(dst, src) \
    asm volatile("cp.async.cg.shared.global [%0], [%1], 16;" :: "r"(dst), "l"(src))
#define CP_COMMIT() asm volatile("cp.async.commit_group;")
#define CP_WAIT(n)  asm volatile("cp.async.wait_group %0;" :: "n"(n))

// ---------------- prep kernels ----------------
__global__ void zero_halo_kernel() {      // zero only the 200 boundary cells of xpad
    int t = blockIdx.x * blockDim.x + threadIdx.x;
    const int total = B_ * 200 * 64;
    if (t >= total) return;
    int q = t & 63;
    int cell = (t >> 6) % 200;
    int b = t / (200 * 64);
    int h, w;
    if      (cell < 51)  { h = 0;  w = cell; }
    else if (cell < 102) { h = 50; w = cell - 51; }
    else if (cell < 151) { h = cell - 101; w = 0; }
    else                 { h = cell - 150; w = 50; }
    ((float4*)(g_xpad + ((size_t)(b * PAD + h) * PAD + w) * C_))[q] =
        make_float4(0.f, 0.f, 0.f, 0.f);
}

__global__ void prep_wb_kernel(const float* __restrict__ w) {
    int idx = blockIdx.x * blockDim.x + threadIdx.x;
    if (idx < O_ * KTOT) {
        int o = idx / KTOT;
        int k = idx - o * KTOT;
        int tap = k >> 8, c = k & 255;
        g_wb[idx] = to_tf32(w[(o * C_ + c) * 7 + tap]);
    }
}

__global__ void prep_x_kernel(const float* __restrict__ x) {
    __shared__ float tile[32][33];
    const int b = blockIdx.z, c0 = blockIdx.y * 32, hw0 = blockIdx.x * 32;
    const int tx = threadIdx.x, ty = threadIdx.y;
#pragma unroll
    for (int i = 0; i < 4; i++) {
        int c = c0 + ty + i * 8, hw = hw0 + tx;
        tile[ty + i * 8][tx] = (hw < P_) ? x[((size_t)b * C_ + c) * P_ + hw] : 0.f;
    }
    __syncthreads();
#pragma unroll
    for (int i = 0; i < 4; i++) {
        int hw = hw0 + ty + i * 8;
        if (hw < P_) {
            int h = hw / H_, w = hw - h * H_;
            bool mk = (unsigned)(h + w - 24) <= 48u;
            float v = mk ? to_tf32(tile[tx][ty + i * 8]) : 0.f;
            g_xpad[((size_t)(b * PAD + h + 1) * PAD + (w + 1)) * C_ + c0 + tx] = v;
        }
    }
}

// ---------------- main: tf32 mma.sync GEMM, 128x128 tile, 3-stage cp.async, 2 CTA/SM ----
__global__ __launch_bounds__(256, 2)
void hexconv_mma_kernel(const float* __restrict__ bias, float* __restrict__ out) {
    extern __shared__ __align__(16) float smem[];
    float* sA = smem;                     // [STAGES][128][36]
    float* sB = smem + STAGES * STAGE_F;  // [STAGES][128][36]
    __shared__ int rbase[MT];

    const int tid = threadIdx.x, wid = tid >> 5, lane = tid & 31;
    const int r0 = blockIdx.x * MT;
    const int nb = blockIdx.y;            // N tile: o-offset nb*128

    if (tid < MT) {
        int r = r0 + tid;
        if (r >= M_) r = M_ - 1;
        int b = r / P_, hw = r - b * P_, h = hw / H_, w = hw - h * H_;
        rbase[tid] = ((b * PAD + h + 1) * PAD + (w + 1)) * C_;
    }
    __syncthreads();

    // loader mapping: thread covers 4 rows (lrow+32i), one 16B quad per row
    const int lrow = tid >> 3;            // 0..31
    const int lq   = (tid & 7) * 4;       // 0,4,...,28 floats
    int ra[4];
#pragma unroll
    for (int i = 0; i < 4; i++) ra[i] = rbase[lrow + 32 * i];

    const uint32_t sA_u = (uint32_t)__cvta_generic_to_shared(sA);
    const uint32_t sB_u = (uint32_t)__cvta_generic_to_shared(sB);

    // warp tile: 2 (M) x 4 (N) warps, each 64x32
    const int wm = (wid & 1) * 64;
    const int wn = (wid >> 1) * 32;

    float acc[4][4][4];
#pragma unroll
    for (int mi = 0; mi < 4; mi++)
#pragma unroll
        for (int ni = 0; ni < 4; ni++)
#pragma unroll
            for (int j = 0; j < 4; j++) acc[mi][ni][j] = 0.f;

    // ---- pipeline ----
    auto load_stage = [&](int s, int ch) {
        const int k0 = ch * KC;
        const int offA = c_tapoff[k0 >> 8] + (k0 & 255) + lq;
#pragma unroll
        for (int i = 0; i < 4; i++) {
            uint32_t dA = sA_u + (uint32_t)(s * STAGE_F + (lrow + 32 * i) * ASTRIDE + lq) * 4u;
            CP_ASYNC16(dA, g_xpad + ra[i] + offA);
        }
#pragma unroll
        for (int i = 0; i < 4; i++) {
            uint32_t dB = sB_u + (uint32_t)(s * STAGE_F + (lrow + 32 * i) * ASTRIDE + lq) * 4u;
            CP_ASYNC16(dB, g_wb + (size_t)(nb * 128 + lrow + 32 * i) * KTOT + k0 + lq);
        }
    };

#pragma unroll
    for (int s = 0; s < STAGES - 1; s++) { load_stage(s, s); CP_COMMIT(); }

    for (int ch = 0; ch < NCHUNK; ch++) {
        CP_WAIT(STAGES - 2);
        __syncthreads();
        const int pre = ch + STAGES - 1;
        if (pre < NCHUNK) load_stage(pre % STAGES, pre);
        CP_COMMIT();

        const float* A = sA + (ch % STAGES) * STAGE_F;
        const float* Bm = sB + (ch % STAGES) * STAGE_F;
#pragma unroll
        for (int kk = 0; kk < 4; kk++) {
            const int kb = kk * 8 + (lane & 3);
            uint32_t af[4][4], bf[4][2];
#pragma unroll
            for (int mi = 0; mi < 4; mi++) {
                int m0 = wm + mi * 16 + (lane >> 2);
                af[mi][0] = __float_as_uint(A[m0 * ASTRIDE + kb]);
                af[mi][1] = __float_as_uint(A[(m0 + 8) * ASTRIDE + kb]);
                af[mi][2] = __float_as_uint(A[m0 * ASTRIDE + kb + 4]);
                af[mi][3] = __float_as_uint(A[(m0 + 8) * ASTRIDE + kb + 4]);
            }
#pragma unroll
            for (int ni = 0; ni < 4; ni++) {
                int n0 = wn + ni * 8 + (lane >> 2);
                bf[ni][0] = __float_as_uint(Bm[n0 * ASTRIDE + kb]);
                bf[ni][1] = __float_as_uint(Bm[n0 * ASTRIDE + kb + 4]);
            }
#pragma unroll
            for (int mi = 0; mi < 4; mi++)
#pragma unroll
                for (int ni = 0; ni < 4; ni++)
                    mma8(acc[mi][ni], af[mi], bf[ni]);
        }
    }

    // ---- epilogue: acc -> smem [o][m] (stride 132), then coalesced store ----
    __syncthreads();
    float* ep = smem;                     // 128*132 floats = 67.6 KB < 110.6 KB
#pragma unroll
    for (int mi = 0; mi < 4; mi++) {
        int rrow = wm + mi * 16 + (lane >> 2);
#pragma unroll
        for (int ni = 0; ni < 4; ni++) {
            int o = wn + ni * 8 + 2 * (lane & 3);
            ep[o * 132 + rrow]           = acc[mi][ni][0];
            ep[(o + 1) * 132 + rrow]     = acc[mi][ni][1];
            ep[o * 132 + rrow + 8]       = acc[mi][ni][2];
            ep[(o + 1) * 132 + rrow + 8] = acc[mi][ni][3];
        }
    }
    __syncthreads();

    for (int o = wid; o < 128; o += 8) {
        float bv = __ldg(bias + nb * 128 + o);
#pragma unroll
        for (int mb = 0; mb < 128; mb += 32) {
            int m = mb + lane;
            int r = r0 + m;
            if (r < M_) {
                int b = r / P_, hw = r - b * P_, h = hw / H_, w = hw - h * H_;
                bool mk = (unsigned)(h + w - 24) <= 48u;
                float v = mk ? (ep[o * 132 + m] + bv) : 0.f;
                out[((size_t)b * O_ + nb * 128 + o) * P_ + hw] = v;
            }
        }
    }
}

// ---------------- launcher ----------------
extern "C" void kernel_launch(void* const* d_in, const int* in_sizes, int n_in,
                              void* d_out, int out_size) {
    const float* x    = (const float*)d_in[0];   // [32,256,49,49]
    const float* wgt  = (const float*)d_in[1];   // [256,256,7]
    const float* bias = (const float*)d_in[2];   // [256]
    float* out = (float*)d_out;

    { // prep
        int nh = B_ * 200 * 64;
        zero_halo_kernel<<<(nh + 255) / 256, 256>>>();
        int nw = O_ * KTOT;
        prep_wb_kernel<<<(nw + 255) / 256, 256>>>(wgt);
        dim3 g((P_ + 31) / 32, C_ / 32, B_);
        prep_x_kernel<<<g, dim3(32, 8)>>>(x);
    }

    cudaFuncSetAttribute(hexconv_mma_kernel,
                         cudaFuncAttributeMaxDynamicSharedMemorySize, DYN_SMEM);
    dim3 grid(GRID_M, 2);
    hexconv_mma_kernel<<<grid, 256, DYN_SMEM>>>(bias, out);
}